// round 11
// baseline (speedup 1.0000x reference)
#include <cuda_runtime.h>
#include <cstdint>

#define H 512
#define W 512
#define NB 32

#define SQRT_APPROX(d, a) \
    asm("sqrt.approx.f32 %0, %1;" : "=f"(d) : "f"(a))

// R6 read path (1 thread = 4 px, shuffle halo, approx sqrt), but stores go
// through a 4KB smem tile + cp.async.bulk (smem -> gmem) x3 channels,
// removing 3x STG.128 per thread from the LSU path.
// Block = 256 threads = 2 full rows. grid = (H/2, NB).
__global__ __launch_bounds__(256) void sqdiff_mag_kernel(
    const float* __restrict__ x, float* __restrict__ out)
{
    __shared__ __align__(16) float tile[2 * W];   // 4 KB: 2 output rows

    int lane = threadIdx.x & 31;
    int wg   = threadIdx.x & 127;                 // float4 group in row
    int h    = (blockIdx.x << 1) + (threadIdx.x >> 7);
    int n    = blockIdx.y;

    int w     = wg << 2;
    int wbase = w & ~127;

    const size_t plane = (size_t)H * W;
    const float* g = x + ((size_t)n * 3 + 1) * plane;   // channel 1

    float rm[6], rc[6], rp[6];

    #define LOAD_ROW(dst, hh)                                                  \
    {                                                                          \
        const float* p = g + (size_t)(hh) * W + w;                             \
        float4 v = *reinterpret_cast<const float4*>(p);                        \
        dst[1] = v.x; dst[2] = v.y; dst[3] = v.z; dst[4] = v.w;                \
        float lft = __shfl_up_sync(0xffffffffu, v.w, 1);                       \
        float rgt = __shfl_down_sync(0xffffffffu, v.x, 1);                     \
        if (lane == 0)  lft = (wbase > 0)       ? __ldg(p - 1) : 0.0f;         \
        if (lane == 31) rgt = (wbase + 128 < W) ? __ldg(p + 4) : 0.0f;         \
        dst[0] = lft; dst[5] = rgt;                                            \
    }

    LOAD_ROW(rc, h)
    if (h > 0) {
        LOAD_ROW(rm, h - 1)
    } else {
        #pragma unroll
        for (int i = 0; i < 6; i++) rm[i] = 0.0f;
    }
    if (h + 1 < H) {
        LOAD_ROW(rp, h + 1)
    } else {
        #pragma unroll
        for (int i = 0; i < 6; i++) rp[i] = 0.0f;
    }
    #undef LOAD_ROW

    float4 res;
    float* resp = reinterpret_cast<float*>(&res);

    #pragma unroll
    for (int i = 0; i < 4; i++) {
        float c  = rc[i + 1];
        float d0 = c - rc[i + 2];
        float d1 = c - rc[i];
        float d2 = c - rp[i + 1];
        float d3 = c - rm[i + 1];
        float d4 = c - rp[i + 2];
        float d5 = c - rp[i];
        float d6 = c - rm[i + 2];
        float d7 = c - rm[i];
        float s = d0 * d0;
        s = fmaf(d1, d1, s);
        s = fmaf(d2, d2, s);
        s = fmaf(d3, d3, s);
        s = fmaf(d4, d4, s);
        s = fmaf(d5, d5, s);
        s = fmaf(d6, d6, s);
        s = fmaf(d7, d7, s);
        SQRT_APPROX(resp[i], s);
    }

    // One STS.128 per thread: tile layout == gmem layout of the 2-row span.
    reinterpret_cast<float4*>(tile)[threadIdx.x] = res;
    __syncthreads();

    // Elected thread pushes the 4KB tile to the 3 channel planes via
    // bulk-async copy (async proxy; reads smem, writes L2/GMEM directly).
    if (threadIdx.x == 0) {
        asm volatile("fence.proxy.async.shared::cta;" ::: "memory");
        uint32_t saddr = (uint32_t)__cvta_generic_to_shared(tile);
        int h0 = blockIdx.x << 1;
        float* ob = out + (size_t)n * 3 * plane + (size_t)h0 * W;
        #pragma unroll
        for (int c = 0; c < 3; c++) {
            asm volatile(
                "cp.async.bulk.global.shared::cta.bulk_group [%0], [%1], %2;"
                :: "l"(ob + (size_t)c * plane), "r"(saddr), "r"(2 * W * 4)
                : "memory");
        }
        asm volatile("cp.async.bulk.commit_group;" ::: "memory");
        // Drain before block exit so smem isn't reallocated under the copy
        // and the writes are complete at kernel end.
        asm volatile("cp.async.bulk.wait_group 0;" ::: "memory");
    }
}

extern "C" void kernel_launch(void* const* d_in, const int* in_sizes, int n_in,
                              void* d_out, int out_size)
{
    const float* x = (const float*)d_in[0];
    float* out = (float*)d_out;

    dim3 grid(H / 2, NB);   // 256 x 32 = 8192 CTAs of 256 threads
    sqdiff_mag_kernel<<<grid, 256>>>(x, out);
}

// round 12
// speedup vs baseline: 1.1133x; 1.1133x over previous
#include <cuda_runtime.h>

#define H 512
#define W 512
#define NB 32

#define SQRT_APPROX(d, a) \
    asm("sqrt.approx.f32 %0, %1;" : "=f"(d) : "f"(a))

// Full-width vertical tile: block = 128 threads = one full 512-px row width.
// Block computes 4 consecutive output rows from 6 input rows (1.5x read amp,
// 6 independent front-batched LDG.128 -> MLP 6). Stores are contiguous
// full-row 2KB bursts x3 planes (no R2/R7 fragmentation).
// grid = (H/4, NB) = (128, 32).
__global__ __launch_bounds__(128) void sqdiff_mag_kernel(
    const float* __restrict__ x, float* __restrict__ out)
{
    int lane  = threadIdx.x & 31;
    int wbase = (threadIdx.x >> 5) << 7;     // warp's 128-px strip start
    int w     = threadIdx.x << 2;            // == wbase + lane*4

    int h0 = blockIdx.x << 2;                // first of 4 output rows
    int n  = blockIdx.y;

    const size_t plane = (size_t)H * W;
    const float* g = x + ((size_t)n * 3 + 1) * plane;   // channel 1

    // rows h0-1 .. h0+4 as cols [w-1 .. w+4]
    float r[6][6];

    #define LOAD_ROW(j, hh, valid)                                             \
    if (valid) {                                                               \
        const float* p = g + (size_t)(hh) * W + w;                             \
        float4 v = *reinterpret_cast<const float4*>(p);                        \
        r[j][1] = v.x; r[j][2] = v.y; r[j][3] = v.z; r[j][4] = v.w;            \
        float lft = __shfl_up_sync(0xffffffffu, v.w, 1);                       \
        float rgt = __shfl_down_sync(0xffffffffu, v.x, 1);                     \
        if (lane == 0)  lft = (wbase > 0)       ? __ldg(p - 1) : 0.0f;         \
        if (lane == 31) rgt = (wbase + 128 < W) ? __ldg(p + 4) : 0.0f;         \
        r[j][0] = lft; r[j][5] = rgt;                                          \
    } else {                                                                   \
        r[j][0] = r[j][1] = r[j][2] = r[j][3] = r[j][4] = r[j][5] = 0.0f;      \
    }

    LOAD_ROW(0, h0 - 1, (h0 > 0))
    LOAD_ROW(1, h0,      true)
    LOAD_ROW(2, h0 + 1,  true)
    LOAD_ROW(3, h0 + 2,  true)
    LOAD_ROW(4, h0 + 3,  true)
    LOAD_ROW(5, h0 + 4, (h0 + 4 < H))
    #undef LOAD_ROW

    float* ob = out + (size_t)n * 3 * plane + (size_t)h0 * W + w;

    #pragma unroll
    for (int rr = 0; rr < 4; rr++) {
        float4 res;
        float* resp = reinterpret_cast<float*>(&res);
        #pragma unroll
        for (int i = 0; i < 4; i++) {
            float c  = r[rr + 1][i + 1];
            float d0 = c - r[rr + 1][i + 2];
            float d1 = c - r[rr + 1][i];
            float d2 = c - r[rr + 2][i + 1];
            float d3 = c - r[rr][i + 1];
            float d4 = c - r[rr + 2][i + 2];
            float d5 = c - r[rr + 2][i];
            float d6 = c - r[rr][i + 2];
            float d7 = c - r[rr][i];
            float s = d0 * d0;
            s = fmaf(d1, d1, s);
            s = fmaf(d2, d2, s);
            s = fmaf(d3, d3, s);
            s = fmaf(d4, d4, s);
            s = fmaf(d5, d5, s);
            s = fmaf(d6, d6, s);
            s = fmaf(d7, d7, s);
            SQRT_APPROX(resp[i], s);
        }
        float* o = ob + (size_t)rr * W;
        __stcs(reinterpret_cast<float4*>(o),             res);
        __stcs(reinterpret_cast<float4*>(o + plane),     res);
        __stcs(reinterpret_cast<float4*>(o + 2 * plane), res);
    }
}

extern "C" void kernel_launch(void* const* d_in, const int* in_sizes, int n_in,
                              void* d_out, int out_size)
{
    const float* x = (const float*)d_in[0];
    float* out = (float*)d_out;

    dim3 grid(H / 4, NB);   // 128 x 32 = 4096 CTAs of 128 threads
    sqdiff_mag_kernel<<<grid, 128>>>(x, out);
}